// round 2
// baseline (speedup 1.0000x reference)
#include <cuda_runtime.h>
#include <math.h>

#define TM 16

// ---------------- scratch (device globals; no allocations allowed) -----------
__device__ float g_Wc [256 * 256];   // Wc[i][j]  = sum_m q_w[i,m] * kv_w[j,m]          (Wk = kv_w[:, :256])
__device__ float g_Wvo[256 * 256];   // Wvo[i][j] = sum_m kv_w[i,256+m] * out_w[m,j]    (Wv@out_w)
__device__ float g_bc [256];         // bc[j]  = sum_m q_b[m]  * kv_w[j,m]
__device__ float g_wbk[256];         // wbk[i] = sum_j q_w[i,j]* kv_b[j]
__device__ float g_bvo[256];         // bvo[j] = sum_m kv_b[256+m] * out_w[m,j]
__device__ float g_tconst;           // q_b . kv_b[:256]

__device__ __forceinline__ float warp_sum(float v) {
    #pragma unroll
    for (int o = 16; o > 0; o >>= 1) v += __shfl_xor_sync(0xFFFFFFFFu, v, o);
    return v;
}

// ---------------- precompute: 256x256x256 mini-GEMMs -------------------------
// MODE 0: C = A @ B        (A[M,K] lda, B[K,N] ldb)
// MODE 1: C = A @ B^T      (A[M,K] lda, B[N,K] ldb)
// DST 0 -> g_Wc, DST 1 -> g_Wvo
template<int MODE, int DST>
__global__ void gemm256_kernel(const float* __restrict__ A, int lda,
                               const float* __restrict__ B, int ldb)
{
    __shared__ float As[32][33];
    __shared__ float Bs[32][33];   // Bs[m][c]
    int tx = threadIdx.x, ty = threadIdx.y;
    int row0 = blockIdx.y * 32, col0 = blockIdx.x * 32;
    float acc[4] = {0.f, 0.f, 0.f, 0.f};
    for (int kt = 0; kt < 256; kt += 32) {
        #pragma unroll
        for (int u = 0; u < 4; u++) {
            As[ty * 4 + u][tx] = A[(row0 + ty * 4 + u) * lda + kt + tx];
            if (MODE == 0)
                Bs[ty * 4 + u][tx] = B[(kt + ty * 4 + u) * ldb + col0 + tx];
            else
                Bs[tx][ty * 4 + u] = B[(col0 + ty * 4 + u) * ldb + kt + tx];
        }
        __syncthreads();
        #pragma unroll
        for (int m = 0; m < 32; m++) {
            float bv = Bs[m][tx];
            #pragma unroll
            for (int u = 0; u < 4; u++)
                acc[u] = fmaf(As[ty * 4 + u][m], bv, acc[u]);
        }
        __syncthreads();
    }
    float* C = (DST == 0) ? g_Wc : g_Wvo;
    #pragma unroll
    for (int u = 0; u < 4; u++)
        C[(row0 + ty * 4 + u) * 256 + col0 + tx] = acc[u];
}

// ---------------- precompute: bias vectors ------------------------------------
__global__ void vecpre_kernel(const float* __restrict__ q_w,
                              const float* __restrict__ q_b,
                              const float* __restrict__ kv_w,
                              const float* __restrict__ kv_b,
                              const float* __restrict__ out_w)
{
    int blk  = blockIdx.x;
    int lane = threadIdx.x & 31;
    int wrp  = threadIdx.x >> 5;
    if (blk < 32) {
        // bc[j] = sum_m q_b[m] * kv_w[j*512 + m]    (warp per j)
        int j = blk * 8 + wrp;
        float s = 0.f;
        #pragma unroll
        for (int k = 0; k < 8; k++) {
            int m = k * 32 + lane;
            s = fmaf(q_b[m], kv_w[j * 512 + m], s);
        }
        s = warp_sum(s);
        if (lane == 0) g_bc[j] = s;
    } else if (blk < 64) {
        // wbk[i] = sum_j q_w[i*256 + j] * kv_b[j]   (warp per i)
        int i = (blk - 32) * 8 + wrp;
        float s = 0.f;
        #pragma unroll
        for (int k = 0; k < 8; k++) {
            int j = k * 32 + lane;
            s = fmaf(q_w[i * 256 + j], kv_b[j], s);
        }
        s = warp_sum(s);
        if (lane == 0) g_wbk[i] = s;
    } else {
        // bvo[j] = sum_m kv_b[256+m] * out_w[m*256 + j]
        int j = threadIdx.x;
        float s = 0.f;
        for (int m = 0; m < 256; m++)
            s = fmaf(kv_b[256 + m], out_w[m * 256 + j], s);
        g_bvo[j] = s;
        if (wrp == 0) {
            float t = 0.f;
            #pragma unroll
            for (int k = 0; k < 8; k++) {
                int m = k * 32 + lane;
                t = fmaf(q_b[m], kv_b[m], t);
            }
            t = warp_sum(t);
            if (lane == 0) g_tconst = t;
        }
    }
}

// ---------------- fully fused main kernel -------------------------------------
// Block handles TM=16 (b,n) rows with 256 threads (8 warps).
__global__ void __launch_bounds__(256)
fused_kernel(const float* __restrict__ queries,
             const float* __restrict__ feats,
             const float* __restrict__ coords,
             const int* __restrict__ valid,
             const float* __restrict__ ln_g,
             const float* __restrict__ ln_b,
             const float* __restrict__ out_b,
             float* __restrict__ out)
{
    __shared__ __align__(16) float qn_s[TM][256];  // qn; reused for mixed in phase 3/4
    __shared__ __align__(16) float qk_s[TM][256];
    __shared__ float t_s[TM];
    __shared__ float s_s[TM];

    int tid  = threadIdx.x;
    int lane = tid & 31;
    int wrp  = tid >> 5;
    int r0   = blockIdx.x * TM;

    // ---- Phase 1: LayerNorm + per-row scalar t = qn.wbk + const (warp-per-row)
    #pragma unroll
    for (int mm = 0; mm < 2; mm++) {
        int m = wrp + mm * 8;
        int r = r0 + m;
        float x[8];
        float s = 0.f;
        #pragma unroll
        for (int k = 0; k < 8; k++) {
            x[k] = queries[r * 256 + k * 32 + lane];
            s += x[k];
        }
        s = warp_sum(s);
        float mu = s * (1.f / 256.f);
        float vv = 0.f;
        #pragma unroll
        for (int k = 0; k < 8; k++) { float d = x[k] - mu; vv = fmaf(d, d, vv); }
        vv = warp_sum(vv);
        float inv = rsqrtf(vv * (1.f / 256.f) + 1e-5f);
        float t = 0.f;
        #pragma unroll
        for (int k = 0; k < 8; k++) {
            int d = k * 32 + lane;
            float q = (x[k] - mu) * inv * ln_g[d] + ln_b[d];
            qn_s[m][d] = q;
            t = fmaf(q, g_wbk[d], t);
        }
        t = warp_sum(t);
        if (lane == 0) t_s[m] = t + g_tconst;
    }
    __syncthreads();

    // ---- Phase 2: qk[m][j] = qn[m] @ Wc + bc[j]   (rank-4 updates, float4 LDS)
    {
        float acc[TM];
        #pragma unroll
        for (int m = 0; m < TM; m++) acc[m] = 0.f;
        const float4* qn4 = (const float4*)&qn_s[0][0];
        #pragma unroll 4
        for (int i4 = 0; i4 < 64; i4++) {
            int i = i4 * 4;
            float w0 = g_Wc[(i + 0) * 256 + tid];
            float w1 = g_Wc[(i + 1) * 256 + tid];
            float w2 = g_Wc[(i + 2) * 256 + tid];
            float w3 = g_Wc[(i + 3) * 256 + tid];
            #pragma unroll
            for (int m = 0; m < TM; m++) {
                float4 q = qn4[m * 64 + i4];
                acc[m] = fmaf(w0, q.x, fmaf(w1, q.y, fmaf(w2, q.z, fmaf(w3, q.w, acc[m]))));
            }
        }
        float b = g_bc[tid];
        #pragma unroll
        for (int m = 0; m < TM; m++) qk_s[m][tid] = acc[m] + b;
    }
    __syncthreads();

    // ---- Phase 3: bilinear sample + logits + softmax + mixed (warp-per-row)
    #pragma unroll
    for (int mm = 0; mm < 2; mm++) {
        int m = wrp + mm * 8;
        int r = r0 + m;
        int bb = r >> 13;     // / 8192
        int n  = r & 8191;
        float vals[6][8];
        float logit[6];
        int   vld[6];
        #pragma unroll
        for (int c = 0; c < 6; c++) {
            int bcidx = bb * 6 + c;
            float px = coords[(bcidx * 8192 + n) * 2 + 0];
            float py = coords[(bcidx * 8192 + n) * 2 + 1];
            float x = (px + 1.f) * 31.5f;    // *0.5*(64-1)
            float y = (py + 1.f) * 31.5f;
            float x0f = floorf(x), y0f = floorf(y);
            int   x0 = (int)x0f,  y0 = (int)y0f;
            float wx1 = x - x0f, wx0 = 1.f - wx1;
            float wy1 = y - y0f, wy0 = 1.f - wy1;
            bool ix0 = (x0 >= 0)  && (x0 <= 63);
            bool ix1 = (x0 >= -1) && (x0 <= 62);
            bool iy0 = (y0 >= 0)  && (y0 <= 63);
            bool iy1 = (y0 >= -1) && (y0 <= 62);
            int cx0 = min(max(x0, 0), 63);
            int cx1 = min(max(x0 + 1, 0), 63);
            int cy0 = min(max(y0, 0), 63);
            int cy1 = min(max(y0 + 1, 0), 63);
            const float* fb  = feats + (size_t)bcidx * 4096 * 256;
            const float* p00 = fb + (cy0 * 64 + cx0) * 256;
            const float* p01 = fb + (cy0 * 64 + cx1) * 256;
            const float* p10 = fb + (cy1 * 64 + cx0) * 256;
            const float* p11 = fb + (cy1 * 64 + cx1) * 256;
            float w00 = (ix0 && iy0) ? wy0 * wx0 : 0.f;
            float w01 = (ix1 && iy0) ? wy0 * wx1 : 0.f;
            float w10 = (ix0 && iy1) ? wy1 * wx0 : 0.f;
            float w11 = (ix1 && iy1) ? wy1 * wx1 : 0.f;
            float dacc = 0.f;
            #pragma unroll
            for (int k = 0; k < 8; k++) {
                int d = k * 32 + lane;
                float v = w00 * p00[d] + w01 * p01[d] + w10 * p10[d] + w11 * p11[d];
                vals[c][k] = v;
                dacc = fmaf(v, qk_s[m][d], dacc);
            }
            dacc = warp_sum(dacc);
            logit[c] = (dacc + t_s[m]) * 0.0625f;   // 1/sqrt(256)
            vld[c]   = (valid[bcidx * 8192 + n] != 0);
        }
        float mx = -1e30f;
        #pragma unroll
        for (int c = 0; c < 6; c++) if (vld[c]) mx = fmaxf(mx, logit[c]);
        float e[6];
        float ssum = 0.f;
        #pragma unroll
        for (int c = 0; c < 6; c++) {
            e[c] = vld[c] ? __expf(logit[c] - mx) : 0.f;
            ssum += e[c];
        }
        float inv = (ssum > 0.f) ? (1.f / ssum) : 0.f;
        float mixed[8];
        #pragma unroll
        for (int k = 0; k < 8; k++) mixed[k] = 0.f;
        #pragma unroll
        for (int c = 0; c < 6; c++) {
            float a = e[c] * inv;
            #pragma unroll
            for (int k = 0; k < 8; k++) mixed[k] = fmaf(a, vals[c][k], mixed[k]);
        }
        #pragma unroll
        for (int k = 0; k < 8; k++) qn_s[m][k * 32 + lane] = mixed[k];
        if (lane == 0) s_s[m] = (ssum > 0.f) ? 1.f : 0.f;
    }
    __syncthreads();

    // ---- Phase 4: final = residual + mixed @ Wvo + s*bvo + out_b
    {
        float acc[TM];
        #pragma unroll
        for (int m = 0; m < TM; m++) acc[m] = 0.f;
        const float4* mx4 = (const float4*)&qn_s[0][0];
        #pragma unroll 4
        for (int i4 = 0; i4 < 64; i4++) {
            int i = i4 * 4;
            float w0 = g_Wvo[(i + 0) * 256 + tid];
            float w1 = g_Wvo[(i + 1) * 256 + tid];
            float w2 = g_Wvo[(i + 2) * 256 + tid];
            float w3 = g_Wvo[(i + 3) * 256 + tid];
            #pragma unroll
            for (int m = 0; m < TM; m++) {
                float4 q = mx4[m * 64 + i4];
                acc[m] = fmaf(w0, q.x, fmaf(w1, q.y, fmaf(w2, q.z, fmaf(w3, q.w, acc[m]))));
            }
        }
        float ob  = out_b[tid];
        float bvv = g_bvo[tid];
        #pragma unroll
        for (int m = 0; m < TM; m++) {
            int r = r0 + m;
            out[r * 256 + tid] = queries[r * 256 + tid] + acc[m] + s_s[m] * bvv + ob;
        }
    }
}

// ---------------- launch ------------------------------------------------------
extern "C" void kernel_launch(void* const* d_in, const int* in_sizes, int n_in,
                              void* d_out, int out_size)
{
    const float* queries = (const float*)d_in[0];
    const float* feats   = (const float*)d_in[1];
    const float* coords  = (const float*)d_in[2];
    const int*   valid   = (const int*)d_in[3];
    const float* q_w     = (const float*)d_in[4];
    const float* q_b     = (const float*)d_in[5];
    const float* kv_w    = (const float*)d_in[6];
    const float* kv_b    = (const float*)d_in[7];
    const float* out_w   = (const float*)d_in[8];
    const float* out_b   = (const float*)d_in[9];
    const float* ln_g    = (const float*)d_in[10];
    const float* ln_b    = (const float*)d_in[11];
    float*       out     = (float*)d_out;

    dim3 gblk(32, 8);
    dim3 ggrd(8, 8);
    // Wc = q_w @ (kv_w[:, :256])^T
    gemm256_kernel<1, 0><<<ggrd, gblk>>>(q_w, 256, kv_w, 512);
    // Wvo = kv_w[:, 256:] @ out_w
    gemm256_kernel<0, 1><<<ggrd, gblk>>>(kv_w + 256, 512, out_w, 256);
    vecpre_kernel<<<65, 256>>>(q_w, q_b, kv_w, kv_b, out_w);

    int rows = 2 * 8192;
    fused_kernel<<<rows / TM, 256>>>(queries, feats, coords, valid,
                                     ln_g, ln_b, out_b, out);
}